// round 15
// baseline (speedup 1.0000x reference)
#include <cuda_runtime.h>
#include <cuda_fp16.h>
#include <math.h>
#include <stdint.h>

#define HD    1024
#define NL4   4
#define SEQ   512
#define NRW   64
#define LO    256
#define LDC   512
#define NPAIR (NRW*3)
#define MR    (NRW*LO)
#define NEGV  -1e30f

// ---------------------------------------------------------------------------
// Static device scratch
// ---------------------------------------------------------------------------
__device__ float  g_opt_enc[MR*HD];
__device__ int    g_opt_mask[MR];
__device__ float  g_doc_enc[NRW*LDC*HD];
__device__ int    g_doc_mask[NRW*LDC];
__device__ float  g_logitOpt[NPAIR*LO*LO];
__device__ float  g_attnOpt[NPAIR*LO*HD];
__device__ __half g_Xh[MR*7*HD];
__device__ __half g_Xl[MR*7*HD];
__device__ __half g_Wh[16*HD*HD];
__device__ float  g_corr[MR*HD];
__device__ float  g_option[MR*HD];
__device__ float  g_logitD[NRW*LO*LDC];
__device__ float  g_attnD[MR*HD];
__device__ float  g_coattn[MR*HD];
__device__ float  g_fusion[MR*HD];
__device__ float  g_logitS[NRW*LO*LO];
__device__ float  g_attn2[MR*HD];
__device__ float  g_fusion2[MR*HD];
__device__ float  g_rowq[MR];
__device__ float  g_rowk[MR];
__device__ float  g_rowkd[NRW*LDC];
// fp16 operand planes for attention GEMMs
__device__ __half g_encOh[MR*HD], g_encOl[MR*HD], g_encOsw[MR*HD];
__device__ __half g_encOT[NRW*HD*LO];
__device__ __half g_encDsw[NRW*LDC*HD];
__device__ __half g_encDT[NRW*HD*LDC];
__device__ __half g_optH[MR*HD], g_optL[MR*HD], g_optT[NRW*HD*LO];
__device__ __half g_fusH[MR*HD], g_fusL[MR*HD], g_fusT[NRW*HD*LO], g_fusSW[MR*HD];
__device__ __half g_awOh[NPAIR*LO*LO], g_awOl[NPAIR*LO*LO];
__device__ __half g_awDh[NRW*LO*LDC], g_awDl[NRW*LO*LDC];
__device__ __half g_kqh[NRW*LO*LDC];
__device__ __half g_cowH[NRW*LO*LO], g_cowL[NRW*LO*LO];
__device__ __half g_awSh[NRW*LO*LO], g_awSl[NRW*LO*LO];

// ---------------------------------------------------------------------------
// Helpers
// ---------------------------------------------------------------------------
__device__ __forceinline__ int read_fp(const int* __restrict__ p, int n)
{
    return (p[1] == 0) ? p[2*n] : p[n];
}

__device__ __forceinline__ void mma_f16(float* c, const uint32_t* a, const uint32_t* b)
{
    asm volatile(
        "mma.sync.aligned.m16n8k16.row.col.f32.f16.f16.f32 "
        "{%0,%1,%2,%3}, {%4,%5,%6,%7}, {%8,%9}, {%0,%1,%2,%3};"
        : "+f"(c[0]), "+f"(c[1]), "+f"(c[2]), "+f"(c[3])
        : "r"(a[0]), "r"(a[1]), "r"(a[2]), "r"(a[3]), "r"(b[0]), "r"(b[1]));
}

__device__ __forceinline__ void wsplit(__half* __restrict__ xh, __half* __restrict__ xl,
                                       size_t i, float x)
{
    __half h = __float2half_rn(x);
    xh[i] = h;
    xl[i] = __float2half_rn(x - __half2float(h));
}

// ---------------------------------------------------------------------------
// Build kernels
// ---------------------------------------------------------------------------
__global__ void k_build_opt(const float* __restrict__ ll, const int* __restrict__ am,
                            const int* __restrict__ fpw)
{
    int o = blockIdx.x, n = blockIdx.y, t = threadIdx.x;
    int fp = read_fp(fpw, n);
    int idx = fp + o;
    int valid = (idx >= 0) && (idx < SEQ);
    int idxc = valid ? idx : (SEQ - 1);
    int m = valid && (am[n*SEQ + idxc] > 0);
    const float4* src = (const float4*)(ll + (size_t)(n*SEQ + idxc) * HD);
    size_t r = (size_t)(n*LO + o);
    float4 v = m ? src[t] : make_float4(0.f,0.f,0.f,0.f);
    ((float4*)(g_opt_enc + r * HD))[t] = v;
    size_t b = r * HD + t*4;
    wsplit(g_encOh, g_encOl, b+0, v.x);
    wsplit(g_encOh, g_encOl, b+1, v.y);
    wsplit(g_encOh, g_encOl, b+2, v.z);
    wsplit(g_encOh, g_encOl, b+3, v.w);
    if (t == 0) g_opt_mask[r] = m;
}

__global__ void k_build_doc(const float* __restrict__ ll, const int* __restrict__ am,
                            const int* __restrict__ fpw)
{
    int t0 = blockIdx.x, n = blockIdx.y, t = threadIdx.x;
    int fp = read_fp(fpw, n);
    int m = (t0 < fp) && (am[n*SEQ + t0] > 0);
    const float4* src = (const float4*)(ll + (size_t)(n*SEQ + t0) * HD);
    float4* dst = (float4*)(g_doc_enc + (size_t)(n*LDC + t0) * HD);
    float4 v = m ? src[t] : make_float4(0.f,0.f,0.f,0.f);
    dst[t] = v;
    if (t == 0) g_doc_mask[n*LDC + t0] = m;
}

__global__ void k_rowdot(const float* __restrict__ X, const float* __restrict__ w,
                         float* __restrict__ out)
{
    int r = blockIdx.x;
    const float* x = X + (size_t)r * HD;
    float s = 0.f;
    for (int i = threadIdx.x; i < HD; i += 256) s += x[i] * w[i];
    __shared__ float sh[256];
    sh[threadIdx.x] = s; __syncthreads();
    for (int st = 128; st > 0; st >>= 1) {
        if (threadIdx.x < st) sh[threadIdx.x] += sh[threadIdx.x + st];
        __syncthreads();
    }
    if (threadIdx.x == 0) out[r] = sh[0];
}

__global__ void k_cvtw(const float* __restrict__ w, __half* __restrict__ o)
{
    int i = blockIdx.x * 256 + threadIdx.x;
    float4 v = ((const float4*)w)[i];
    ((__half2*)o)[2*i]   = __floats2half2_rn(v.x, v.y);
    ((__half2*)o)[2*i+1] = __floats2half2_rn(v.z, v.w);
}

// out[i] = fp16(in[i] * w[i % HD])   (per-column scale, row width HD)
__global__ void k_scale16(const float* __restrict__ in, const float* __restrict__ w,
                          __half* __restrict__ o)
{
    size_t i = (size_t)blockIdx.x * 256 + threadIdx.x;
    o[i] = __float2half_rn(in[i] * w[i & (HD-1)]);
}

// per-batch transpose: in[b][R][HD] fp32 -> out[b][HD][R] fp16
__global__ void k_transpose16(const float* __restrict__ in, __half* __restrict__ o, int R)
{
    __shared__ float tile[32][33];
    int b = blockIdx.z;
    int r0 = blockIdx.x * 32, h0 = blockIdx.y * 32;
    const float* ib = in + (size_t)b * R * HD;
    __half* ob = o + (size_t)b * HD * R;
    int x = threadIdx.x, y = threadIdx.y;
#pragma unroll
    for (int dy = 0; dy < 32; dy += 8)
        tile[y+dy][x] = ib[(size_t)(r0 + y + dy) * HD + h0 + x];
    __syncthreads();
#pragma unroll
    for (int dy = 0; dy < 32; dy += 8)
        ob[(size_t)(h0 + y + dy) * R + r0 + x] = __float2half_rn(tile[x][y+dy]);
}

// ---------------------------------------------------------------------------
// Shared 2xFP16 NT MMA core pieces (128x128x16 tiles, 8 warps, 2 CTA/SM)
// ---------------------------------------------------------------------------
#define PT    544
#define PLANE (8*PT)
#define BUFB  (3*PLANE)

// ---------------------------------------------------------------------------
// FC GEMM (M = MR rows): C = act(X @ W^T + bias)
// EPI: 1=tanh 2=relu 3=sigmoid-gate 4=tanh + fp16 hi/lo plane out
// ---------------------------------------------------------------------------
template<int EPI>
__global__ __launch_bounds__(256, 2) void k_fc_mma(
    const __half* __restrict__ Ah_g, const __half* __restrict__ Al_g,
    const __half* __restrict__ Bw,
    float* __restrict__ C, int K,
    const float* __restrict__ bias,
    const float* __restrict__ E1, const float* __restrict__ E2,
    __half* __restrict__ Ch, __half* __restrict__ Cl)
{
    __shared__ __align__(16) char sm[2*BUFB];
    const int tid = threadIdx.x;
    const int lane = tid & 31, wid = tid >> 5;
    const int wm = wid & 1, wn = wid >> 1;
    const int g = lane >> 2, t = lane & 3;
    const int bm = blockIdx.y << 7, bn = blockIdx.x << 7;

    float acc[4][4][4];
#pragma unroll
    for (int i = 0; i < 4; i++)
#pragma unroll
        for (int q = 0; q < 4; q++)
#pragma unroll
            for (int c = 0; c < 4; c++) acc[i][q][c] = 0.f;

    const int prow = tid & 127;
    const bool isA = tid < 128;
    const __half* srcH = isA ? (Ah_g + (size_t)(bm + prow) * K)
                             : (Bw   + (size_t)(bn + prow) * K);
    const __half* srcL = Al_g + (size_t)(bm + prow) * K;
    uint4 f0, f1, f2, f3;

    auto fetch = [&](int ch) {
        const __half* p = srcH + (ch << 4);
        f0 = *(const uint4*)p;
        f1 = *(const uint4*)(p + 8);
        if (isA) {
            const __half* q = srcL + (ch << 4);
            f2 = *(const uint4*)q;
            f3 = *(const uint4*)(q + 8);
        }
    };
    auto store_buf = [&](int buf) {
        char* d = sm + buf*BUFB + (isA ? 0 : 2*PLANE) + prow*4;
        *(uint32_t*)(d + 0*PT) = f0.x; *(uint32_t*)(d + 1*PT) = f0.y;
        *(uint32_t*)(d + 2*PT) = f0.z; *(uint32_t*)(d + 3*PT) = f0.w;
        *(uint32_t*)(d + 4*PT) = f1.x; *(uint32_t*)(d + 5*PT) = f1.y;
        *(uint32_t*)(d + 6*PT) = f1.z; *(uint32_t*)(d + 7*PT) = f1.w;
        if (isA) {
            char* dl = d + PLANE;
            *(uint32_t*)(dl + 0*PT) = f2.x; *(uint32_t*)(dl + 1*PT) = f2.y;
            *(uint32_t*)(dl + 2*PT) = f2.z; *(uint32_t*)(dl + 3*PT) = f2.w;
            *(uint32_t*)(dl + 4*PT) = f3.x; *(uint32_t*)(dl + 5*PT) = f3.y;
            *(uint32_t*)(dl + 6*PT) = f3.z; *(uint32_t*)(dl + 7*PT) = f3.w;
        }
    };

    const int T = K >> 4;
    fetch(0);
    store_buf(0);
    __syncthreads();

    for (int ch = 0; ch < T; ++ch) {
        const int buf = ch & 1;
        if (ch + 1 < T) fetch(ch + 1);
        const char* Ah = sm + buf*BUFB;
        const char* Al = Ah + PLANE;
        const char* Bh = Ah + 2*PLANE;
        const int rA = (wm << 6) + g;
        const int rB = (wn << 5) + g;
        uint32_t ah[4][4], al[4][4], bh[4][2];
#pragma unroll
        for (int i = 0; i < 4; i++) {
            const char* p = Ah + t*PT + (rA + (i << 4)) * 4;
            ah[i][0] = *(const uint32_t*)p;
            ah[i][1] = *(const uint32_t*)(p + 32);
            ah[i][2] = *(const uint32_t*)(p + 4*PT);
            ah[i][3] = *(const uint32_t*)(p + 4*PT + 32);
        }
#pragma unroll
        for (int q = 0; q < 4; q++) {
            const char* p = Bh + t*PT + (rB + (q << 3)) * 4;
            bh[q][0] = *(const uint32_t*)p;
            bh[q][1] = *(const uint32_t*)(p + 4*PT);
        }
#pragma unroll
        for (int i = 0; i < 4; i++)
#pragma unroll
            for (int q = 0; q < 4; q++) mma_f16(acc[i][q], ah[i], bh[q]);
#pragma unroll
        for (int i = 0; i < 4; i++) {
            const char* p = Al + t*PT + (rA + (i << 4)) * 4;
            al[i][0] = *(const uint32_t*)p;
            al[i][1] = *(const uint32_t*)(p + 32);
            al[i][2] = *(const uint32_t*)(p + 4*PT);
            al[i][3] = *(const uint32_t*)(p + 4*PT + 32);
        }
#pragma unroll
        for (int i = 0; i < 4; i++)
#pragma unroll
            for (int q = 0; q < 4; q++) mma_f16(acc[i][q], al[i], bh[q]);
        if (ch + 1 < T) store_buf(buf ^ 1);
        __syncthreads();
    }

#pragma unroll
    for (int i = 0; i < 4; i++) {
        int row0 = bm + (wm << 6) + (i << 4) + g;
#pragma unroll
        for (int q = 0; q < 4; q++) {
            int col = bn + (wn << 5) + (q << 3) + (t << 1);
            float b0 = bias[col], b1 = bias[col + 1];
#pragma unroll
            for (int h = 0; h < 2; h++) {
                int row = row0 + h * 8;
                float v0 = acc[i][q][h*2+0] + b0;
                float v1 = acc[i][q][h*2+1] + b1;
                size_t ci = (size_t)row * HD + col;
                float2 o;
                if (EPI == 1 || EPI == 4) { o.x = tanhf(v0); o.y = tanhf(v1); }
                else if (EPI == 2) { o.x = fmaxf(v0, 0.f); o.y = fmaxf(v1, 0.f); }
                else {
                    float g0 = 1.f / (1.f + expf(-v0));
                    float g1 = 1.f / (1.f + expf(-v1));
                    o.x = E1[ci]   * g0 + E2[ci]   * (1.f - g0);
                    o.y = E1[ci+1] * g1 + E2[ci+1] * (1.f - g1);
                }
                *(float2*)(C + ci) = o;
                if (EPI == 3 || EPI == 4) {   // also emit fp16 hi/lo planes
                    wsplit(Ch, Cl, ci, o.x);
                    wsplit(Ch, Cl, ci + 1, o.y);
                }
            }
        }
    }
}

// ---------------------------------------------------------------------------
// Attention GEMM (M = 256 per batch): C = A(hi+lo) @ B^T
// EPI: 0=plain f32  4=trilinear logits  5=fp16 hi/lo pair out
// PM:  0=strided batches  1=logitOpt pairs (A per n, B per mb)
//      2=attnOpt pairs (A per z, B per mb)
// ---------------------------------------------------------------------------
template<int EPI, int PM>
__global__ __launch_bounds__(256, 2) void k_att_mma(
    const __half* __restrict__ Ah_g, const __half* __restrict__ Al_g,
    const __half* __restrict__ Bh_g,
    float* __restrict__ C, __half* __restrict__ Ch, __half* __restrict__ Cl,
    int N, int K,
    long sA, long sB, long sC,
    const float* __restrict__ ql, const float* __restrict__ kl,
    const int* __restrict__ mq, const int* __restrict__ mk,
    long sQl, long sKl)
{
    __shared__ __align__(16) char sm[2*BUFB];
    const int tid = threadIdx.x;
    const int lane = tid & 31, wid = tid >> 5;
    const int wm = wid & 1, wn = wid >> 1;
    const int g = lane >> 2, t = lane & 3;
    const int bm = blockIdx.y << 7, bn = blockIdx.x << 7;
    const int z = blockIdx.z;

    long offA, offB, offC, offQl = 0, offKl = 0;
    if (PM == 1 || PM == 2) {
        int n = z / 3, jj = z % 3;
        int b = n / NL4, i = n % NL4;
        int j = jj + (jj >= i ? 1 : 0);
        int mb = b * NL4 + j;
        offA = (PM == 1 ? (long)n : (long)z) * LO * K;
        offB = (long)mb * (long)N * K;   // PM1: N=LO; PM2: N=HD rows of encOT
        offC = (long)z * LO * N;
        offQl = (long)n * LO; offKl = (long)mb * LO;
    } else {
        offA = z * sA; offB = z * sB; offC = z * sC;
        offQl = z * sQl; offKl = z * sKl;
    }

    float acc[4][4][4];
#pragma unroll
    for (int i = 0; i < 4; i++)
#pragma unroll
        for (int q = 0; q < 4; q++)
#pragma unroll
            for (int c = 0; c < 4; c++) acc[i][q][c] = 0.f;

    const int prow = tid & 127;
    const bool isA = tid < 128;
    const __half* srcH = isA ? (Ah_g + offA + (size_t)(bm + prow) * K)
                             : (Bh_g + offB + (size_t)(bn + prow) * K);
    const __half* srcL = Al_g + offA + (size_t)(bm + prow) * K;
    uint4 f0, f1, f2, f3;

    auto fetch = [&](int ch) {
        const __half* p = srcH + (ch << 4);
        f0 = *(const uint4*)p;
        f1 = *(const uint4*)(p + 8);
        if (isA) {
            const __half* q = srcL + (ch << 4);
            f2 = *(const uint4*)q;
            f3 = *(const uint4*)(q + 8);
        }
    };
    auto store_buf = [&](int buf) {
        char* d = sm + buf*BUFB + (isA ? 0 : 2*PLANE) + prow*4;
        *(uint32_t*)(d + 0*PT) = f0.x; *(uint32_t*)(d + 1*PT) = f0.y;
        *(uint32_t*)(d + 2*PT) = f0.z; *(uint32_t*)(d + 3*PT) = f0.w;
        *(uint32_t*)(d + 4*PT) = f1.x; *(uint32_t*)(d + 5*PT) = f1.y;
        *(uint32_t*)(d + 6*PT) = f1.z; *(uint32_t*)(d + 7*PT) = f1.w;
        if (isA) {
            char* dl = d + PLANE;
            *(uint32_t*)(dl + 0*PT) = f2.x; *(uint32_t*)(dl + 1*PT) = f2.y;
            *(uint32_t*)(dl + 2*PT) = f2.z; *(uint32_t*)(dl + 3*PT) = f2.w;
            *(uint32_t*)(dl + 4*PT) = f3.x; *(uint32_t*)(dl + 5*PT) = f3.y;
            *(uint32_t*)(dl + 6*PT) = f3.z; *(uint32_t*)(dl + 7*PT) = f3.w;
        }
    };

    const int T = K >> 4;
    fetch(0);
    store_buf(0);
    __syncthreads();

    for (int ch = 0; ch < T; ++ch) {
        const int buf = ch & 1;
        if (ch + 1 < T) fetch(ch + 1);
        const char* Ah = sm + buf*BUFB;
        const char* Al = Ah + PLANE;
        const char* Bh = Ah + 2*PLANE;
        const int rA = (wm << 6) + g;
        const int rB = (wn << 5) + g;
        uint32_t ah[4][4], al[4][4], bh[4][2];
#pragma unroll
        for (int i = 0; i < 4; i++) {
            const char* p = Ah + t*PT + (rA + (i << 4)) * 4;
            ah[i][0] = *(const uint32_t*)p;
            ah[i][1] = *(const uint32_t*)(p + 32);
            ah[i][2] = *(const uint32_t*)(p + 4*PT);
            ah[i][3] = *(const uint32_t*)(p + 4*PT + 32);
        }
#pragma unroll
        for (int q = 0; q < 4; q++) {
            const char* p = Bh + t*PT + (rB + (q << 3)) * 4;
            bh[q][0] = *(const uint32_t*)p;
            bh[q][1] = *(const uint32_t*)(p + 4*PT);
        }
#pragma unroll
        for (int i = 0; i < 4; i++)
#pragma unroll
            for (int q = 0; q < 4; q++) mma_f16(acc[i][q], ah[i], bh[q]);
#pragma unroll
        for (int i = 0; i < 4; i++) {
            const char* p = Al + t*PT + (rA + (i << 4)) * 4;
            al[i][0] = *(const uint32_t*)p;
            al[i][1] = *(const uint32_t*)(p + 32);
            al[i][2] = *(const uint32_t*)(p + 4*PT);
            al[i][3] = *(const uint32_t*)(p + 4*PT + 32);
        }
#pragma unroll
        for (int i = 0; i < 4; i++)
#pragma unroll
            for (int q = 0; q < 4; q++) mma_f16(acc[i][q], al[i], bh[q]);
        if (ch + 1 < T) store_buf(buf ^ 1);
        __syncthreads();
    }

#pragma unroll
    for (int i = 0; i < 4; i++) {
        int row0 = bm + (wm << 6) + (i << 4) + g;
#pragma unroll
        for (int q = 0; q < 4; q++) {
            int col = bn + (wn << 5) + (q << 3) + (t << 1);
#pragma unroll
            for (int h = 0; h < 2; h++) {
                int row = row0 + h * 8;
                float v0 = acc[i][q][h*2+0];
                float v1 = acc[i][q][h*2+1];
                size_t ci = offC + (size_t)row * N + col;
                if (EPI == 0) {
                    *(float2*)(C + ci) = make_float2(v0, v1);
                } else if (EPI == 4) {
                    float qlv = ql[offQl + row];
                    int qmv = mq[offQl + row];
                    float2 o;
                    o.x = (qmv && mk[offKl + col])   ? v0 + qlv + kl[offKl + col]   : NEGV;
                    o.y = (qmv && mk[offKl + col+1]) ? v1 + qlv + kl[offKl + col+1] : NEGV;
                    *(float2*)(C + ci) = o;
                } else {
                    wsplit(Ch, Cl, ci, v0);
                    wsplit(Ch, Cl, ci + 1, v1);
                }
            }
        }
    }
}

// ---------------------------------------------------------------------------
// Softmax kernels (emit fp16 hi/lo aw planes)
// ---------------------------------------------------------------------------
__global__ void k_row_softmax(const float* __restrict__ X,
    __half* __restrict__ awh, __half* __restrict__ awl, int Cdim,
    const int* __restrict__ mqb, const int* __restrict__ mkb,
    long sX, long sMq, long sMk, int pairMode)
{
    int z = blockIdx.y, row = blockIdx.x;
    long offX, offMq, offMk;
    if (pairMode) {
        int n = z / 3, jj = z % 3;
        int b = n / NL4, i = n % NL4;
        int j = jj + (jj >= i ? 1 : 0);
        int mb = b * NL4 + j;
        offX = (long)z * LO * LO; offMq = (long)n * LO; offMk = (long)mb * LO;
    } else { offX = z * sX; offMq = z * sMq; offMk = z * sMk; }
    const float* x = X + offX + (long)row * Cdim;
    __half* yh = awh + offX + (long)row * Cdim;
    __half* yl = awl + offX + (long)row * Cdim;
    const int* mk = mkb + offMk;
    int qm = mqb[offMq + row];
    int tid = threadIdx.x;
    __shared__ float sh[256];
    float mx = -3.4e38f;
    for (int c = tid; c < Cdim; c += 256) mx = fmaxf(mx, x[c]);
    sh[tid] = mx; __syncthreads();
    for (int s = 128; s > 0; s >>= 1) {
        if (tid < s) sh[tid] = fmaxf(sh[tid], sh[tid + s]);
        __syncthreads();
    }
    mx = sh[0]; __syncthreads();
    float sum = 0.f;
    for (int c = tid; c < Cdim; c += 256) sum += expf(x[c] - mx);
    sh[tid] = sum; __syncthreads();
    for (int s = 128; s > 0; s >>= 1) {
        if (tid < s) sh[tid] += sh[tid + s];
        __syncthreads();
    }
    float inv = 1.f / sh[0];
    for (int c = tid; c < Cdim; c += 256) {
        float e = expf(x[c] - mx);
        float w = (qm && mk[c]) ? e * inv : 0.f;
        __half h = __float2half_rn(w);
        yh[c] = h;
        yl[c] = __float2half_rn(w - __half2float(h));
    }
}

__global__ void k_col_softmax()
{
    int n = blockIdx.y;
    int t = blockIdx.x * 256 + threadIdx.x;
    const float* x = g_logitD + (size_t)n * LO * LDC;
    float mx = -3.4e38f;
    for (int o = 0; o < LO; o++) mx = fmaxf(mx, x[(size_t)o * LDC + t]);
    float sum = 0.f;
    for (int o = 0; o < LO; o++) sum += expf(x[(size_t)o * LDC + t] - mx);
    float inv = 1.f / sum;
    int km = g_doc_mask[n*LDC + t];
    __half* y = g_kqh + (size_t)n * LO * LDC;
    for (int o = 0; o < LO; o++) {
        float e = expf(x[(size_t)o * LDC + t] - mx);
        y[(size_t)o * LDC + t] =
            __float2half_rn((km && g_opt_mask[n*LO + o]) ? e * inv : 0.f);
    }
}

// ---------------------------------------------------------------------------
// Concat builders + final max
// ---------------------------------------------------------------------------
__global__ void k_feats()
{
    size_t idx = (size_t)blockIdx.x * 256 + threadIdx.x;
    size_t r = idx >> 10;
    int h = (int)(idx & 1023);
    int n = (int)(r >> 8);
    int o = (int)(r & 255);
    float cur = g_opt_enc[idx];
    __half* xh = g_Xh + r * (7*HD);
    __half* xl = g_Xl + r * (7*HD);
    wsplit(xh, xl, h, cur);
#pragma unroll
    for (int jj = 0; jj < 3; jj++) {
        float a = g_attnOpt[(((size_t)(n*3 + jj) * LO + o) << 10) + h];
        wsplit(xh, xl, (size_t)(1 + 2*jj)*HD + h, cur * a);
        wsplit(xh, xl, (size_t)(2 + 2*jj)*HD + h, cur - a);
    }
}

__global__ void k_concat2()
{
    size_t idx = (size_t)blockIdx.x * 256 + threadIdx.x;
    size_t r = idx >> 10;
    int h = (int)(idx & 1023);
    __half* xh = g_Xh + r * (2*HD);
    __half* xl = g_Xl + r * (2*HD);
    wsplit(xh, xl, h, g_opt_enc[idx]);
    wsplit(xh, xl, (size_t)HD + h, g_corr[idx]);
}

__global__ void k_concat3()
{
    size_t idx = (size_t)blockIdx.x * 256 + threadIdx.x;
    size_t r = idx >> 10;
    int h = (int)(idx & 1023);
    __half* xh = g_Xh + r * (3*HD);
    __half* xl = g_Xl + r * (3*HD);
    wsplit(xh, xl, h, g_option[idx]);
    wsplit(xh, xl, (size_t)HD + h, g_attnD[idx]);
    wsplit(xh, xl, (size_t)2*HD + h, g_coattn[idx]);
}

__global__ void k_concat4()
{
    size_t idx = (size_t)blockIdx.x * 256 + threadIdx.x;
    size_t r = idx >> 10;
    int h = (int)(idx & 1023);
    float f = g_fusion[idx];
    float a = g_attn2[idx];
    __half* xh = g_Xh + r * (4*HD);
    __half* xl = g_Xl + r * (4*HD);
    wsplit(xh, xl, h, f);
    wsplit(xh, xl, (size_t)HD + h, a);
    wsplit(xh, xl, (size_t)2*HD + h, f * a);
    wsplit(xh, xl, (size_t)3*HD + h, f - a);
}

__global__ void k_final(float* __restrict__ out)
{
    int n = blockIdx.y;
    int h = blockIdx.x * 256 + threadIdx.x;
    float mx = NEGV;
    for (int o = 0; o < LO; o++) {
        if (g_opt_mask[n*LO + o])
            mx = fmaxf(mx, g_fusion2[((size_t)(n*LO + o) << 10) + h]);
    }
    out[(size_t)n * HD + h] = mx;
}

// ---------------------------------------------------------------------------
// Launch
// ---------------------------------------------------------------------------
extern "C" void kernel_launch(void* const* d_in, const int* in_sizes, int n_in,
                              void* d_out, int out_size)
{
    const float* ll  = (const float*)d_in[0];
    const int*   am  = (const int*)d_in[1];
    const int*   fpw = (const int*)d_in[2];
    int base = (in_sizes[3] <= 8) ? 4 : 3;
    const float* attn_w1   = (const float*)d_in[base+0];
    const float* attn_w2   = (const float*)d_in[base+1];
    const float* attn_w3   = (const float*)d_in[base+2];
    const float* opt_w1    = (const float*)d_in[base+3];
    const float* opt_w2    = (const float*)d_in[base+4];
    const float* opt_w3    = (const float*)d_in[base+5];
    const float* self_w1   = (const float*)d_in[base+6];
    const float* self_w2   = (const float*)d_in[base+7];
    const float* self_w3   = (const float*)d_in[base+8];
    const float* attn_fc_w = (const float*)d_in[base+9];
    const float* attn_fc_b = (const float*)d_in[base+10];
    const float* comp_fc_w = (const float*)d_in[base+11];
    const float* comp_fc_b = (const float*)d_in[base+12];
    const float* gate_fc_w = (const float*)d_in[base+13];
    const float* gate_fc_b = (const float*)d_in[base+14];
    const float* self_fc_w = (const float*)d_in[base+15];
    const float* self_fc_b = (const float*)d_in[base+16];
    float* out = (float*)d_out;

    float *opt_enc, *doc_enc, *logitOpt, *attnOpt, *corr, *option;
    float *logitD, *attnD, *coattn, *fusion, *logitS, *attn2, *fusion2;
    float *rowq, *rowk, *rowkd;
    __half *Xh, *Xl, *Wh;
    __half *encOh, *encOl, *encOsw, *encOT, *encDsw, *encDT;
    __half *optH, *optL, *optT, *fusH, *fusL, *fusT, *fusSW;
    __half *awOh, *awOl, *awDh, *awDl, *kqh, *cowH, *cowL, *awSh, *awSl;
    int *opt_mask, *doc_mask;
    cudaGetSymbolAddress((void**)&opt_enc,  g_opt_enc);
    cudaGetSymbolAddress((void**)&doc_enc,  g_doc_enc);
    cudaGetSymbolAddress((void**)&logitOpt, g_logitOpt);
    cudaGetSymbolAddress((void**)&attnOpt,  g_attnOpt);
    cudaGetSymbolAddress((void**)&Xh,       g_Xh);
    cudaGetSymbolAddress((void**)&Xl,       g_Xl);
    cudaGetSymbolAddress((void**)&Wh,       g_Wh);
    cudaGetSymbolAddress((void**)&corr,     g_corr);
    cudaGetSymbolAddress((void**)&option,   g_option);
    cudaGetSymbolAddress((void**)&logitD,   g_logitD);
    cudaGetSymbolAddress((void**)&attnD,    g_attnD);
    cudaGetSymbolAddress((void**)&coattn,   g_coattn);
    cudaGetSymbolAddress((void**)&fusion,   g_fusion);
    cudaGetSymbolAddress((void**)&logitS,   g_logitS);
    cudaGetSymbolAddress((void**)&attn2,    g_attn2);
    cudaGetSymbolAddress((void**)&fusion2,  g_fusion2);
    cudaGetSymbolAddress((void**)&rowq,     g_rowq);
    cudaGetSymbolAddress((void**)&rowk,     g_rowk);
    cudaGetSymbolAddress((void**)&rowkd,    g_rowkd);
    cudaGetSymbolAddress((void**)&encOh,    g_encOh);
    cudaGetSymbolAddress((void**)&encOl,    g_encOl);
    cudaGetSymbolAddress((void**)&encOsw,   g_encOsw);
    cudaGetSymbolAddress((void**)&encOT,    g_encOT);
    cudaGetSymbolAddress((void**)&encDsw,   g_encDsw);
    cudaGetSymbolAddress((void**)&encDT,    g_encDT);
    cudaGetSymbolAddress((void**)&optH,     g_optH);
    cudaGetSymbolAddress((void**)&optL,     g_optL);
    cudaGetSymbolAddress((void**)&optT,     g_optT);
    cudaGetSymbolAddress((void**)&fusH,     g_fusH);
    cudaGetSymbolAddress((void**)&fusL,     g_fusL);
    cudaGetSymbolAddress((void**)&fusT,     g_fusT);
    cudaGetSymbolAddress((void**)&fusSW,    g_fusSW);
    cudaGetSymbolAddress((void**)&awOh,     g_awOh);
    cudaGetSymbolAddress((void**)&awOl,     g_awOl);
    cudaGetSymbolAddress((void**)&awDh,     g_awDh);
    cudaGetSymbolAddress((void**)&awDl,     g_awDl);
    cudaGetSymbolAddress((void**)&kqh,      g_kqh);
    cudaGetSymbolAddress((void**)&cowH,     g_cowH);
    cudaGetSymbolAddress((void**)&cowL,     g_cowL);
    cudaGetSymbolAddress((void**)&awSh,     g_awSh);
    cudaGetSymbolAddress((void**)&awSl,     g_awSl);
    cudaGetSymbolAddress((void**)&opt_mask, g_opt_mask);
    cudaGetSymbolAddress((void**)&doc_mask, g_doc_mask);

    __half* Wcomp = Wh;
    __half* Wgate = Wh + (size_t)7*HD*HD;
    __half* Wattn = Wh + (size_t)9*HD*HD;
    __half* Wself = Wh + (size_t)12*HD*HD;

    const int EW_BLOCKS = (MR * HD) / 256;
    const dim3 FC_GRID(HD/128, MR/128);

    // 0) fp16 weights
    k_cvtw<<<(7*HD*HD/4)/256, 256>>>(comp_fc_w, Wcomp);
    k_cvtw<<<(2*HD*HD/4)/256, 256>>>(gate_fc_w, Wgate);
    k_cvtw<<<(3*HD*HD/4)/256, 256>>>(attn_fc_w, Wattn);
    k_cvtw<<<(4*HD*HD/4)/256, 256>>>(self_fc_w, Wself);

    // 1) build encodings + fp16 operand prep
    k_build_opt<<<dim3(LO,  NRW), 256>>>(ll, am, fpw);
    k_build_doc<<<dim3(LDC, NRW), 256>>>(ll, am, fpw);
    k_scale16<<<(MR*HD)/256, 256>>>(opt_enc, opt_w3, encOsw);
    k_transpose16<<<dim3(LO/32, HD/32, NRW), dim3(32,8)>>>(opt_enc, encOT, LO);
    k_scale16<<<(NRW*LDC*HD)/256, 256>>>(doc_enc, attn_w3, encDsw);
    k_transpose16<<<dim3(LDC/32, HD/32, NRW), dim3(32,8)>>>(doc_enc, encDT, LDC);

    // 2) opt-opt cross attention (192 pairs)
    k_rowdot<<<MR, 256>>>(opt_enc, opt_w1, rowq);
    k_rowdot<<<MR, 256>>>(opt_enc, opt_w2, rowk);
    k_att_mma<4,1><<<dim3(2, 2, NPAIR), 256>>>(
        encOh, encOl, encOsw, logitOpt, nullptr, nullptr, LO, HD,
        0,0,0, rowq, rowk, opt_mask, opt_mask, 0,0);
    k_row_softmax<<<dim3(LO, NPAIR), 256>>>(logitOpt, awOh, awOl, LO,
        opt_mask, opt_mask, 0,0,0, 1);
    k_att_mma<0,2><<<dim3(8, 2, NPAIR), 256>>>(
        awOh, awOl, encOT, attnOpt, nullptr, nullptr, HD, LO,
        0,0,0, nullptr, nullptr, nullptr, nullptr, 0,0);

    // 3) comp FC (K = 7H)
    k_feats<<<EW_BLOCKS, 256>>>();
    k_fc_mma<1><<<FC_GRID, 256>>>(Xh, Xl, Wcomp, corr, 7*HD, comp_fc_b,
                                  nullptr, nullptr, nullptr, nullptr);

    // 4) gate FC (K = 2H) -> option (+ fp16 planes)
    k_concat2<<<EW_BLOCKS, 256>>>();
    k_fc_mma<3><<<FC_GRID, 256>>>(Xh, Xl, Wgate, option, 2*HD, gate_fc_b,
                                  opt_enc, corr, optH, optL);
    k_transpose16<<<dim3(LO/32, HD/32, NRW), dim3(32,8)>>>(option, optT, LO);

    // 5) doc attention (with co-attention)
    k_rowdot<<<MR, 256>>>(option, attn_w1, rowq);
    k_rowdot<<<NRW*LDC, 256>>>(doc_enc, attn_w2, rowkd);
    k_att_mma<4,0><<<dim3(LDC/128, 2, NRW), 256>>>(
        optH, optL, encDsw, logitD, nullptr, nullptr, LDC, HD,
        (long)LO*HD, (long)LDC*HD, (long)LO*LDC,
        rowq, rowkd, opt_mask, doc_mask, LO, LDC);
    k_col_softmax<<<dim3(LDC/256, NRW), 256>>>();
    k_row_softmax<<<dim3(LO, NRW), 256>>>(logitD, awDh, awDl, LDC,
        opt_mask, doc_mask, (long)LO*LDC, LO, LDC, 0);
    k_att_mma<0,0><<<dim3(8, 2, NRW), 256>>>(
        awDh, awDl, encDT, attnD, nullptr, nullptr, HD, LDC,
        (long)LO*LDC, (long)HD*LDC, (long)LO*HD,
        nullptr, nullptr, nullptr, nullptr, 0,0);
    k_att_mma<5,0><<<dim3(2, 2, NRW), 256>>>(
        awDh, awDl, kqh, nullptr, cowH, cowL, LO, LDC,
        (long)LO*LDC, (long)LO*LDC, (long)LO*LO,
        nullptr, nullptr, nullptr, nullptr, 0,0);
    k_att_mma<0,0><<<dim3(8, 2, NRW), 256>>>(
        cowH, cowL, optT, coattn, nullptr, nullptr, HD, LO,
        (long)LO*LO, (long)HD*LO, (long)LO*HD,
        nullptr, nullptr, nullptr, nullptr, 0,0);

    // 6) attn FC (K = 3H) -> fusion (+ fp16 planes)
    k_concat3<<<EW_BLOCKS, 256>>>();
    k_fc_mma<4><<<FC_GRID, 256>>>(Xh, Xl, Wattn, fusion, 3*HD, attn_fc_b,
                                  nullptr, nullptr, fusH, fusL);
    k_transpose16<<<dim3(LO/32, HD/32, NRW), dim3(32,8)>>>(fusion, fusT, LO);
    k_scale16<<<(MR*HD)/256, 256>>>(fusion, self_w3, fusSW);

    // 7) self attention
    k_rowdot<<<MR, 256>>>(fusion, self_w1, rowq);
    k_rowdot<<<MR, 256>>>(fusion, self_w2, rowk);
    k_att_mma<4,0><<<dim3(2, 2, NRW), 256>>>(
        fusH, fusL, fusSW, logitS, nullptr, nullptr, LO, HD,
        (long)LO*HD, (long)LO*HD, (long)LO*LO,
        rowq, rowk, opt_mask, opt_mask, LO, LO);
    k_row_softmax<<<dim3(LO, NRW), 256>>>(logitS, awSh, awSl, LO,
        opt_mask, opt_mask, (long)LO*LO, LO, LO, 0);
    k_att_mma<0,0><<<dim3(8, 2, NRW), 256>>>(
        awSh, awSl, fusT, attn2, nullptr, nullptr, HD, LO,
        (long)LO*LO, (long)HD*LO, (long)LO*HD,
        nullptr, nullptr, nullptr, nullptr, 0,0);

    // 8) self FC (K = 4H) -> fusion2
    k_concat4<<<EW_BLOCKS, 256>>>();
    k_fc_mma<2><<<FC_GRID, 256>>>(Xh, Xl, Wself, fusion2, 4*HD, self_fc_b,
                                  nullptr, nullptr, nullptr, nullptr);

    // 9) masked max over option positions
    k_final<<<dim3(HD/256, NRW), 256>>>(out);
}

// round 16
// speedup vs baseline: 1.6580x; 1.6580x over previous
#include <cuda_runtime.h>
#include <cuda_fp16.h>
#include <math.h>
#include <stdint.h>

#define HD    1024
#define NL4   4
#define SEQ   512
#define NRW   64
#define LO    256
#define LDC   512
#define NPAIR (NRW*3)
#define MR    (NRW*LO)
#define NEGV  -1e30f

// ---------------------------------------------------------------------------
// Static device scratch
// ---------------------------------------------------------------------------
__device__ float  g_opt_enc[MR*HD];
__device__ int    g_opt_mask[MR];
__device__ float  g_doc_enc[NRW*LDC*HD];
__device__ int    g_doc_mask[NRW*LDC];
__device__ float  g_logitOpt[NPAIR*LO*LO];
__device__ float  g_attnOpt[NPAIR*LO*HD];
__device__ __half g_Xh[MR*7*HD];          // FC input, single rn fp16 plane
__device__ __half g_Wh[16*HD*HD];         // fp16 weights: comp|gate|attn|self
__device__ float  g_corr[MR*HD];
__device__ float  g_option[MR*HD];
__device__ float  g_logitD[NRW*LO*LDC];
__device__ float  g_kq[NRW*LO*LDC];
__device__ float  g_attnD[MR*HD];
__device__ float  g_cow[NRW*LO*LO];
__device__ float  g_coattn[MR*HD];
__device__ float  g_fusion[MR*HD];
__device__ float  g_logitS[NRW*LO*LO];
__device__ float  g_attn2[MR*HD];
__device__ float  g_fusion2[MR*HD];
__device__ float  g_rowq[MR];
__device__ float  g_rowk[MR];
__device__ float  g_rowkd[NRW*LDC];

// ---------------------------------------------------------------------------
// Helpers
// ---------------------------------------------------------------------------
__device__ __forceinline__ int read_fp(const int* __restrict__ p, int n)
{
    return (p[1] == 0) ? p[2*n] : p[n];   // int64 vs int32 sniff (values 300..450)
}

__device__ __forceinline__ void mma_f16(float* c, const uint32_t* a, const uint32_t* b)
{
    asm volatile(
        "mma.sync.aligned.m16n8k16.row.col.f32.f16.f16.f32 "
        "{%0,%1,%2,%3}, {%4,%5,%6,%7}, {%8,%9}, {%0,%1,%2,%3};"
        : "+f"(c[0]), "+f"(c[1]), "+f"(c[2]), "+f"(c[3])
        : "r"(a[0]), "r"(a[1]), "r"(a[2]), "r"(a[3]), "r"(b[0]), "r"(b[1]));
}

// ---------------------------------------------------------------------------
// Build kernels
// ---------------------------------------------------------------------------
__global__ void k_build_opt(const float* __restrict__ ll, const int* __restrict__ am,
                            const int* __restrict__ fpw)
{
    int o = blockIdx.x, n = blockIdx.y, t = threadIdx.x;
    int fp = read_fp(fpw, n);
    int idx = fp + o;
    int valid = (idx >= 0) && (idx < SEQ);
    int idxc = valid ? idx : (SEQ - 1);
    int m = valid && (am[n*SEQ + idxc] > 0);
    const float4* src = (const float4*)(ll + (size_t)(n*SEQ + idxc) * HD);
    float4* dst = (float4*)(g_opt_enc + (size_t)(n*LO + o) * HD);
    float4 v = m ? src[t] : make_float4(0.f,0.f,0.f,0.f);
    dst[t] = v;
    if (t == 0) g_opt_mask[n*LO + o] = m;
}

__global__ void k_build_doc(const float* __restrict__ ll, const int* __restrict__ am,
                            const int* __restrict__ fpw)
{
    int t0 = blockIdx.x, n = blockIdx.y, t = threadIdx.x;
    int fp = read_fp(fpw, n);
    int m = (t0 < fp) && (am[n*SEQ + t0] > 0);
    const float4* src = (const float4*)(ll + (size_t)(n*SEQ + t0) * HD);
    float4* dst = (float4*)(g_doc_enc + (size_t)(n*LDC + t0) * HD);
    float4 v = m ? src[t] : make_float4(0.f,0.f,0.f,0.f);
    dst[t] = v;
    if (t == 0) g_doc_mask[n*LDC + t0] = m;
}

__global__ void k_rowdot(const float* __restrict__ X, const float* __restrict__ w,
                         float* __restrict__ out)
{
    int r = blockIdx.x;
    const float* x = X + (size_t)r * HD;
    float s = 0.f;
    for (int i = threadIdx.x; i < HD; i += 256) s += x[i] * w[i];
    __shared__ float sh[256];
    sh[threadIdx.x] = s; __syncthreads();
    for (int st = 128; st > 0; st >>= 1) {
        if (threadIdx.x < st) sh[threadIdx.x] += sh[threadIdx.x + st];
        __syncthreads();
    }
    if (threadIdx.x == 0) out[r] = sh[0];
}

// weight fp32 -> fp16 (rn), elementwise
__global__ void k_cvtw(const float* __restrict__ w, __half* __restrict__ o)
{
    int i = blockIdx.x * 256 + threadIdx.x;
    float4 v = ((const float4*)w)[i];
    ((__half2*)o)[2*i]   = __floats2half2_rn(v.x, v.y);
    ((__half2*)o)[2*i+1] = __floats2half2_rn(v.z, v.w);
}

// ---------------------------------------------------------------------------
// fp32 SGEMMs (attention path) — unchanged
// ---------------------------------------------------------------------------
template<int EPI>   // 0=none 4=trilinear logits
__global__ __launch_bounds__(256) void k_gemm_nt(
    const float* __restrict__ A, const float* __restrict__ B, float* __restrict__ C,
    int M, int N, int K,
    long sA, long sB, long sC,
    const float* __restrict__ colScale,
    const float* __restrict__ ql, const float* __restrict__ kl,
    const int* __restrict__ mq, const int* __restrict__ mk,
    long sQl, long sKl,
    int pairMode)
{
    __shared__ float As[8][128];
    __shared__ float Bs[8][128];
    const int z = blockIdx.z;
    long offA, offB, offC, offQl, offKl;
    if (pairMode) {
        int n = z / 3, jj = z % 3;
        int b = n / NL4, i = n % NL4;
        int j = jj + (jj >= i ? 1 : 0);
        int mb = b * NL4 + j;
        offA = (long)n * LO * HD; offB = (long)mb * LO * HD;
        offC = (long)z * M * N;
        offQl = (long)n * LO; offKl = (long)mb * LO;
    } else {
        offA = z * sA; offB = z * sB; offC = z * sC;
        offQl = z * sQl; offKl = z * sKl;
    }
    const float* Ab = A + offA;
    const float* Bb = B + offB;
    const int tid = threadIdx.x;
    const int bm = blockIdx.y * 128, bn = blockIdx.x * 128;
    const int lr = tid >> 1, lc = (tid & 1) * 4;
    const int ty = tid >> 4, tx = tid & 15;
    float acc[8][8];
#pragma unroll
    for (int i = 0; i < 8; i++)
#pragma unroll
        for (int j = 0; j < 8; j++) acc[i][j] = 0.f;

    for (int k0 = 0; k0 < K; k0 += 8) {
        float4 av = *(const float4*)(Ab + (size_t)(bm + lr) * K + k0 + lc);
        float4 bv = *(const float4*)(Bb + (size_t)(bn + lr) * K + k0 + lc);
        if (EPI == 4) {
            bv.x *= colScale[k0 + lc];     bv.y *= colScale[k0 + lc + 1];
            bv.z *= colScale[k0 + lc + 2]; bv.w *= colScale[k0 + lc + 3];
        }
        As[lc][lr] = av.x; As[lc+1][lr] = av.y; As[lc+2][lr] = av.z; As[lc+3][lr] = av.w;
        Bs[lc][lr] = bv.x; Bs[lc+1][lr] = bv.y; Bs[lc+2][lr] = bv.z; Bs[lc+3][lr] = bv.w;
        __syncthreads();
#pragma unroll
        for (int kk = 0; kk < 8; kk++) {
            float a[8], b[8];
#pragma unroll
            for (int u = 0; u < 8; u++) { a[u] = As[kk][ty*8+u]; b[u] = Bs[kk][tx*8+u]; }
#pragma unroll
            for (int i = 0; i < 8; i++)
#pragma unroll
                for (int j = 0; j < 8; j++) acc[i][j] += a[i] * b[j];
        }
        __syncthreads();
    }
#pragma unroll
    for (int i = 0; i < 8; i++) {
        int m = bm + ty * 8 + i;
#pragma unroll
        for (int j = 0; j < 8; j++) {
            int nn = bn + tx * 8 + j;
            size_t ci = (size_t)offC + (size_t)m * N + nn;
            float v = acc[i][j];
            if (EPI == 0) C[ci] = v;
            else {
                v += ql[offQl + m] + kl[offKl + nn];
                C[ci] = (mq[offQl + m] && mk[offKl + nn]) ? v : NEGV;
            }
        }
    }
}

__global__ __launch_bounds__(256) void k_gemm_nn(
    const float* __restrict__ A, const float* __restrict__ B, float* __restrict__ C,
    int M, int N, int K, long sA, long sB, long sC, int pairMode)
{
    __shared__ float As[8][128];
    __shared__ float Bs[8][128];
    int z = blockIdx.z;
    long offA, offB, offC;
    if (pairMode) {
        int n = z / 3, jj = z % 3;
        int b = n / NL4, i = n % NL4;
        int j = jj + (jj >= i ? 1 : 0);
        int mb = b * NL4 + j;
        offA = (long)z * LO * LO; offB = (long)mb * LO * HD; offC = (long)z * LO * HD;
    } else { offA = z * sA; offB = z * sB; offC = z * sC; }
    const float* Ab = A + offA;
    const float* Bb = B + offB;
    int tid = threadIdx.x;
    int bm = blockIdx.y * 128, bn = blockIdx.x * 128;
    int lr = tid >> 1, lc = (tid & 1) * 4;
    int br = tid >> 5, bc = (tid & 31) * 4;
    int ty = tid >> 4, tx = tid & 15;
    float acc[8][8];
#pragma unroll
    for (int i = 0; i < 8; i++)
#pragma unroll
        for (int j = 0; j < 8; j++) acc[i][j] = 0.f;

    for (int k0 = 0; k0 < K; k0 += 8) {
        float4 av = *(const float4*)(Ab + (size_t)(bm + lr) * K + k0 + lc);
        As[lc][lr] = av.x; As[lc+1][lr] = av.y; As[lc+2][lr] = av.z; As[lc+3][lr] = av.w;
        float4 bv = *(const float4*)(Bb + (size_t)(k0 + br) * N + bn + bc);
        *(float4*)&Bs[br][bc] = bv;
        __syncthreads();
#pragma unroll
        for (int kk = 0; kk < 8; kk++) {
            float a[8], b[8];
#pragma unroll
            for (int u = 0; u < 8; u++) { a[u] = As[kk][ty*8+u]; b[u] = Bs[kk][tx*8+u]; }
#pragma unroll
            for (int i = 0; i < 8; i++)
#pragma unroll
                for (int j = 0; j < 8; j++) acc[i][j] += a[i] * b[j];
        }
        __syncthreads();
    }
#pragma unroll
    for (int i = 0; i < 8; i++) {
        int m = bm + ty * 8 + i;
#pragma unroll
        for (int j = 0; j < 8; j++) {
            int nn = bn + tx * 8 + j;
            C[(size_t)offC + (size_t)m * N + nn] = acc[i][j];
        }
    }
}

// ---------------------------------------------------------------------------
// Single-pass FP16 mma.sync FC GEMM: C[MR,HD] = act(Xh @ Wh^T + bias)
// Both operands pre-rounded rn fp16 (independent ~2^-12 errors; measured
// B-only config gave 1.3e-4 overall; A+B predicted ~2e-4, gate is 1e-3).
// Producer = pure uint4 copy. One barrier/chunk; 2 CTAs/SM.
// EPI: 1=tanh(+bias) 2=relu(+bias) 3=sigmoid gate: C = E1*g + E2*(1-g)
// ---------------------------------------------------------------------------
#define PT    544                  // bytes between k-pair planes' rows
#define PLANE (8*PT)               // 4352 B (8 k-pairs x 128 rows x half2)
#define BUFB  (2*PLANE)            // Ahi, Bhi

template<int EPI>
__global__ __launch_bounds__(256, 2) void k_fc_mma(
    const __half* __restrict__ Ah_g, const __half* __restrict__ Bw,
    float* __restrict__ C, int K,
    const float* __restrict__ bias,
    const float* __restrict__ E1, const float* __restrict__ E2)
{
    __shared__ __align__(16) char sm[2*BUFB];   // 17408 B
    const int tid = threadIdx.x;
    const int lane = tid & 31, wid = tid >> 5;
    const int wm = wid & 1, wn = wid >> 1;
    const int g = lane >> 2, t = lane & 3;
    const int bm = blockIdx.y << 7, bn = blockIdx.x << 7;

    float acc[4][4][4];
#pragma unroll
    for (int i = 0; i < 4; i++)
#pragma unroll
        for (int q = 0; q < 4; q++)
#pragma unroll
            for (int c = 0; c < 4; c++) acc[i][q][c] = 0.f;

    // Producer: threads 0..127 own one A row, 128..255 one B row (16 k each).
    const int prow = tid & 127;
    const bool isA = tid < 128;
    const __half* srcH = isA ? (Ah_g + (size_t)(bm + prow) * K)
                             : (Bw   + (size_t)(bn + prow) * K);
    uint4 f0, f1;

    auto fetch = [&](int ch) {
        const __half* p = srcH + (ch << 4);
        f0 = *(const uint4*)p;
        f1 = *(const uint4*)(p + 8);
    };
    auto store_buf = [&](int buf) {
        char* d = sm + buf*BUFB + (isA ? 0 : PLANE) + prow*4;
        *(uint32_t*)(d + 0*PT) = f0.x; *(uint32_t*)(d + 1*PT) = f0.y;
        *(uint32_t*)(d + 2*PT) = f0.z; *(uint32_t*)(d + 3*PT) = f0.w;
        *(uint32_t*)(d + 4*PT) = f1.x; *(uint32_t*)(d + 5*PT) = f1.y;
        *(uint32_t*)(d + 6*PT) = f1.z; *(uint32_t*)(d + 7*PT) = f1.w;
    };

    const int T = K >> 4;
    fetch(0);
    store_buf(0);
    __syncthreads();

    for (int ch = 0; ch < T; ++ch) {
        const int buf = ch & 1;
        if (ch + 1 < T) fetch(ch + 1);

        const char* Ah = sm + buf*BUFB;
        const char* Bh = Ah + PLANE;
        const int rA = (wm << 6) + g;
        const int rB = (wn << 5) + g;

        uint32_t ah[4][4], bh[4][2];
#pragma unroll
        for (int i = 0; i < 4; i++) {
            const char* p = Ah + t*PT + (rA + (i << 4)) * 4;
            ah[i][0] = *(const uint32_t*)p;
            ah[i][1] = *(const uint32_t*)(p + 32);          // row + 8
            ah[i][2] = *(const uint32_t*)(p + 4*PT);        // k-pair t+4
            ah[i][3] = *(const uint32_t*)(p + 4*PT + 32);
        }
#pragma unroll
        for (int q = 0; q < 4; q++) {
            const char* p = Bh + t*PT + (rB + (q << 3)) * 4;
            bh[q][0] = *(const uint32_t*)p;
            bh[q][1] = *(const uint32_t*)(p + 4*PT);
        }
#pragma unroll
        for (int i = 0; i < 4; i++)
#pragma unroll
            for (int q = 0; q < 4; q++) mma_f16(acc[i][q], ah[i], bh[q]);

        // Producer store overlaps other warps' MMA; one barrier per chunk.
        if (ch + 1 < T) store_buf(buf ^ 1);
        __syncthreads();
    }

    // Epilogue
#pragma unroll
    for (int i = 0; i < 4; i++) {
        int row0 = bm + (wm << 6) + (i << 4) + g;
#pragma unroll
        for (int q = 0; q < 4; q++) {
            int col = bn + (wn << 5) + (q << 3) + (t << 1);
            float b0 = bias[col], b1 = bias[col + 1];
#pragma unroll
            for (int h = 0; h < 2; h++) {
                int row = row0 + h * 8;
                float v0 = acc[i][q][h*2+0] + b0;
                float v1 = acc[i][q][h*2+1] + b1;
                size_t ci = (size_t)row * HD + col;
                float2 o;
                if (EPI == 1)      { o.x = tanhf(v0);        o.y = tanhf(v1); }
                else if (EPI == 2) { o.x = fmaxf(v0, 0.f);   o.y = fmaxf(v1, 0.f); }
                else {
                    float g0 = 1.f / (1.f + expf(-v0));
                    float g1 = 1.f / (1.f + expf(-v1));
                    o.x = E1[ci]   * g0 + E2[ci]   * (1.f - g0);
                    o.y = E1[ci+1] * g1 + E2[ci+1] * (1.f - g1);
                }
                *(float2*)(C + ci) = o;
            }
        }
    }
}

// ---------------------------------------------------------------------------
// Softmax kernels
// ---------------------------------------------------------------------------
__global__ void k_row_softmax(float* __restrict__ X, int Cdim,
    const int* __restrict__ mqb, const int* __restrict__ mkb,
    long sX, long sMq, long sMk, int pairMode)
{
    int z = blockIdx.y, row = blockIdx.x;
    long offX, offMq, offMk;
    if (pairMode) {
        int n = z / 3, jj = z % 3;
        int b = n / NL4, i = n % NL4;
        int j = jj + (jj >= i ? 1 : 0);
        int mb = b * NL4 + j;
        offX = (long)z * LO * LO; offMq = (long)n * LO; offMk = (long)mb * LO;
    } else { offX = z * sX; offMq = z * sMq; offMk = z * sMk; }
    float* x = X + offX + (long)row * Cdim;
    const int* mk = mkb + offMk;
    int qm = mqb[offMq + row];
    int tid = threadIdx.x;
    __shared__ float sh[256];
    float mx = -3.4e38f;
    for (int c = tid; c < Cdim; c += 256) mx = fmaxf(mx, x[c]);
    sh[tid] = mx; __syncthreads();
    for (int s = 128; s > 0; s >>= 1) {
        if (tid < s) sh[tid] = fmaxf(sh[tid], sh[tid + s]);
        __syncthreads();
    }
    mx = sh[0]; __syncthreads();
    float sum = 0.f;
    for (int c = tid; c < Cdim; c += 256) sum += expf(x[c] - mx);
    sh[tid] = sum; __syncthreads();
    for (int s = 128; s > 0; s >>= 1) {
        if (tid < s) sh[tid] += sh[tid + s];
        __syncthreads();
    }
    float inv = 1.f / sh[0];
    for (int c = tid; c < Cdim; c += 256) {
        float e = expf(x[c] - mx);
        x[c] = (qm && mk[c]) ? e * inv : 0.f;
    }
}

__global__ void k_col_softmax()
{
    int n = blockIdx.y;
    int t = blockIdx.x * 256 + threadIdx.x;
    const float* x = g_logitD + (size_t)n * LO * LDC;
    float mx = -3.4e38f;
    for (int o = 0; o < LO; o++) mx = fmaxf(mx, x[(size_t)o * LDC + t]);
    float sum = 0.f;
    for (int o = 0; o < LO; o++) sum += expf(x[(size_t)o * LDC + t] - mx);
    float inv = 1.f / sum;
    int km = g_doc_mask[n*LDC + t];
    float* y = g_kq + (size_t)n * LO * LDC;
    for (int o = 0; o < LO; o++) {
        float e = expf(x[(size_t)o * LDC + t] - mx);
        y[(size_t)o * LDC + t] = (km && g_opt_mask[n*LO + o]) ? e * inv : 0.f;
    }
}

// ---------------------------------------------------------------------------
// Concat builders (emit single rn fp16 plane) + final max
// ---------------------------------------------------------------------------
__global__ void k_feats()
{
    size_t idx = (size_t)blockIdx.x * 256 + threadIdx.x;
    size_t r = idx >> 10;
    int h = (int)(idx & 1023);
    int n = (int)(r >> 8);
    int o = (int)(r & 255);
    float cur = g_opt_enc[idx];
    __half* xh = g_Xh + r * (7*HD);
    xh[h] = __float2half_rn(cur);
#pragma unroll
    for (int jj = 0; jj < 3; jj++) {
        float a = g_attnOpt[(((size_t)(n*3 + jj) * LO + o) << 10) + h];
        xh[(size_t)(1 + 2*jj)*HD + h] = __float2half_rn(cur * a);
        xh[(size_t)(2 + 2*jj)*HD + h] = __float2half_rn(cur - a);
    }
}

__global__ void k_concat2()
{
    size_t idx = (size_t)blockIdx.x * 256 + threadIdx.x;
    size_t r = idx >> 10;
    int h = (int)(idx & 1023);
    __half* xh = g_Xh + r * (2*HD);
    xh[h] = __float2half_rn(g_opt_enc[idx]);
    xh[(size_t)HD + h] = __float2half_rn(g_corr[idx]);
}

__global__ void k_concat3()
{
    size_t idx = (size_t)blockIdx.x * 256 + threadIdx.x;
    size_t r = idx >> 10;
    int h = (int)(idx & 1023);
    __half* xh = g_Xh + r * (3*HD);
    xh[h] = __float2half_rn(g_option[idx]);
    xh[(size_t)HD + h] = __float2half_rn(g_attnD[idx]);
    xh[(size_t)2*HD + h] = __float2half_rn(g_coattn[idx]);
}

__global__ void k_concat4()
{
    size_t idx = (size_t)blockIdx.x * 256 + threadIdx.x;
    size_t r = idx >> 10;
    int h = (int)(idx & 1023);
    float f = g_fusion[idx];
    float a = g_attn2[idx];
    __half* xh = g_Xh + r * (4*HD);
    xh[h] = __float2half_rn(f);
    xh[(size_t)HD + h] = __float2half_rn(a);
    xh[(size_t)2*HD + h] = __float2half_rn(f * a);
    xh[(size_t)3*HD + h] = __float2half_rn(f - a);
}

__global__ void k_final(float* __restrict__ out)
{
    int n = blockIdx.y;
    int h = blockIdx.x * 256 + threadIdx.x;
    float mx = NEGV;
    for (int o = 0; o < LO; o++) {
        if (g_opt_mask[n*LO + o])
            mx = fmaxf(mx, g_fusion2[((size_t)(n*LO + o) << 10) + h]);
    }
    out[(size_t)n * HD + h] = mx;
}

// ---------------------------------------------------------------------------
// Launch
// ---------------------------------------------------------------------------
extern "C" void kernel_launch(void* const* d_in, const int* in_sizes, int n_in,
                              void* d_out, int out_size)
{
    const float* ll  = (const float*)d_in[0];
    const int*   am  = (const int*)d_in[1];
    const int*   fpw = (const int*)d_in[2];
    int base = (in_sizes[3] <= 8) ? 4 : 3;
    const float* attn_w1   = (const float*)d_in[base+0];
    const float* attn_w2   = (const float*)d_in[base+1];
    const float* attn_w3   = (const float*)d_in[base+2];
    const float* opt_w1    = (const float*)d_in[base+3];
    const float* opt_w2    = (const float*)d_in[base+4];
    const float* opt_w3    = (const float*)d_in[base+5];
    const float* self_w1   = (const float*)d_in[base+6];
    const float* self_w2   = (const float*)d_in[base+7];
    const float* self_w3   = (const float*)d_in[base+8];
    const float* attn_fc_w = (const float*)d_in[base+9];
    const float* attn_fc_b = (const float*)d_in[base+10];
    const float* comp_fc_w = (const float*)d_in[base+11];
    const float* comp_fc_b = (const float*)d_in[base+12];
    const float* gate_fc_w = (const float*)d_in[base+13];
    const float* gate_fc_b = (const float*)d_in[base+14];
    const float* self_fc_w = (const float*)d_in[base+15];
    const float* self_fc_b = (const float*)d_in[base+16];
    float* out = (float*)d_out;

    float *opt_enc, *doc_enc, *logitOpt, *attnOpt, *corr, *option;
    float *logitD, *kq, *attnD, *cow, *coattn, *fusion, *logitS, *attn2, *fusion2;
    float *rowq, *rowk, *rowkd;
    __half *Xh, *Wh;
    int *opt_mask, *doc_mask;
    cudaGetSymbolAddress((void**)&opt_enc,  g_opt_enc);
    cudaGetSymbolAddress((void**)&doc_enc,  g_doc_enc);
    cudaGetSymbolAddress((void**)&logitOpt, g_logitOpt);
    cudaGetSymbolAddress((void**)&attnOpt,  g_attnOpt);
    cudaGetSymbolAddress((void**)&Xh,       g_Xh);
    cudaGetSymbolAddress((void**)&Wh,       g_Wh);
    cudaGetSymbolAddress((void**)&corr,     g_corr);
    cudaGetSymbolAddress((void**)&option,   g_option);
    cudaGetSymbolAddress((void**)&logitD,   g_logitD);
    cudaGetSymbolAddress((void**)&kq,       g_kq);
    cudaGetSymbolAddress((void**)&attnD,    g_attnD);
    cudaGetSymbolAddress((void**)&cow,      g_cow);
    cudaGetSymbolAddress((void**)&coattn,   g_coattn);
    cudaGetSymbolAddress((void**)&fusion,   g_fusion);
    cudaGetSymbolAddress((void**)&logitS,   g_logitS);
    cudaGetSymbolAddress((void**)&attn2,    g_attn2);
    cudaGetSymbolAddress((void**)&fusion2,  g_fusion2);
    cudaGetSymbolAddress((void**)&rowq,     g_rowq);
    cudaGetSymbolAddress((void**)&rowk,     g_rowk);
    cudaGetSymbolAddress((void**)&rowkd,    g_rowkd);
    cudaGetSymbolAddress((void**)&opt_mask, g_opt_mask);
    cudaGetSymbolAddress((void**)&doc_mask, g_doc_mask);

    __half* Wcomp = Wh;
    __half* Wgate = Wh + (size_t)7*HD*HD;
    __half* Wattn = Wh + (size_t)9*HD*HD;
    __half* Wself = Wh + (size_t)12*HD*HD;

    const int EW_BLOCKS = (MR * HD) / 256;   // 65536
    const dim3 FC_GRID(HD/128, MR/128);      // 8 x 128

    // 0) convert FC weights to fp16 once
    k_cvtw<<<(7*HD*HD/4)/256, 256>>>(comp_fc_w, Wcomp);
    k_cvtw<<<(2*HD*HD/4)/256, 256>>>(gate_fc_w, Wgate);
    k_cvtw<<<(3*HD*HD/4)/256, 256>>>(attn_fc_w, Wattn);
    k_cvtw<<<(4*HD*HD/4)/256, 256>>>(self_fc_w, Wself);

    // 1) build encodings + masks
    k_build_opt<<<dim3(LO,  NRW), 256>>>(ll, am, fpw);
    k_build_doc<<<dim3(LDC, NRW), 256>>>(ll, am, fpw);

    // 2) opt-opt cross attention (192 pairs)
    k_rowdot<<<MR, 256>>>(opt_enc, opt_w1, rowq);
    k_rowdot<<<MR, 256>>>(opt_enc, opt_w2, rowk);
    k_gemm_nt<4><<<dim3(LO/128, LO/128, NPAIR), 256>>>(
        opt_enc, opt_enc, logitOpt, LO, LO, HD, 0,0,0,
        opt_w3, rowq, rowk, opt_mask, opt_mask, 0,0, 1);
    k_row_softmax<<<dim3(LO, NPAIR), 256>>>(logitOpt, LO, opt_mask, opt_mask, 0,0,0, 1);
    k_gemm_nn<<<dim3(HD/128, LO/128, NPAIR), 256>>>(
        logitOpt, opt_enc, attnOpt, LO, HD, LO, 0,0,0, 1);

    // 3) comp FC (K = 7H), single-pass fp16
    k_feats<<<EW_BLOCKS, 256>>>();
    k_fc_mma<1><<<FC_GRID, 256>>>(Xh, Wcomp, corr, 7*HD, comp_fc_b, nullptr, nullptr);

    // 4) gate FC (K = 2H) with fused gate-combine -> option
    k_concat2<<<EW_BLOCKS, 256>>>();
    k_fc_mma<3><<<FC_GRID, 256>>>(Xh, Wgate, option, 2*HD, gate_fc_b, opt_enc, corr);

    // 5) doc attention (with co-attention)
    k_rowdot<<<MR, 256>>>(option, attn_w1, rowq);
    k_rowdot<<<NRW*LDC, 256>>>(doc_enc, attn_w2, rowkd);
    k_gemm_nt<4><<<dim3(LDC/128, LO/128, NRW), 256>>>(
        option, doc_enc, logitD, LO, LDC, HD,
        (long)LO*HD, (long)LDC*HD, (long)LO*LDC,
        attn_w3, rowq, rowkd, opt_mask, doc_mask, LO, LDC, 0);
    k_col_softmax<<<dim3(LDC/256, NRW), 256>>>();
    k_row_softmax<<<dim3(LO, NRW), 256>>>(logitD, LDC, opt_mask, doc_mask,
        (long)LO*LDC, LO, LDC, 0);
    k_gemm_nn<<<dim3(HD/128, LO/128, NRW), 256>>>(
        logitD, doc_enc, attnD, LO, HD, LDC,
        (long)LO*LDC, (long)LDC*HD, (long)LO*HD, 0);
    k_gemm_nt<0><<<dim3(LO/128, LO/128, NRW), 256>>>(
        logitD, kq, cow, LO, LO, LDC,
        (long)LO*LDC, (long)LO*LDC, (long)LO*LO,
        nullptr, nullptr, nullptr, nullptr, nullptr, 0,0, 0);
    k_gemm_nn<<<dim3(HD/128, LO/128, NRW), 256>>>(
        cow, option, coattn, LO, HD, LO,
        (long)LO*LO, (long)LO*HD, (long)LO*HD, 0);

    // 6) attn FC (K = 3H) -> fusion
    k_concat3<<<EW_BLOCKS, 256>>>();
    k_fc_mma<1><<<FC_GRID, 256>>>(Xh, Wattn, fusion, 3*HD, attn_fc_b, nullptr, nullptr);

    // 7) self attention
    k_rowdot<<<MR, 256>>>(fusion, self_w1, rowq);
    k_rowdot<<<MR, 256>>>(fusion, self_w2, rowk);
    k_gemm_nt<4><<<dim3(LO/128, LO/128, NRW), 256>>>(
        fusion, fusion, logitS, LO, LO, HD,
        (long)LO*HD, (long)LO*HD, (long)LO*LO,
        self_w3, rowq, rowk, opt_mask, opt_mask, LO, LO, 0);
    k_row_softmax<<<dim3(LO, NRW), 256>>>(logitS, LO, opt_mask, opt_mask,
        (long)LO*LO, LO, LO, 0);
    k_gemm_nn<<<dim3(HD/128, LO/128, NRW), 256>>>(
        logitS, fusion, attn2, LO, HD, LO,
        (long)LO*LO, (long)LO*HD, (long)LO*HD, 0);

    // 8) self FC (K = 4H) -> fusion2
    k_concat4<<<EW_BLOCKS, 256>>>();
    k_fc_mma<2><<<FC_GRID, 256>>>(Xh, Wself, fusion2, 4*HD, self_fc_b, nullptr, nullptr);

    // 9) masked max over option positions
    k_final<<<dim3(HD/256, NRW), 256>>>(out);
}